// round 1
// baseline (speedup 1.0000x reference)
#include <cuda_runtime.h>
#include <math.h>

#define BATCH 1024
#define C0 512
#define HW0 196   /* 14*14 */
#define C1 1024
#define HW1 49    /* 7*7  */
#define K0 100
#define K1 50
#define BPB 8     /* batch rows per head block */

// ---------------- scratch (device globals; no allocation) ----------------
__device__ float g_pooled0[BATCH * C0];
__device__ float g_pooled1[BATCH * C1];
__device__ float g_nll[2 * BATCH];   // w[t]*nll per sample, head0 then head1
__device__ float g_ws [2 * BATCH];   // w[t] per sample

// ---------------- pooling: feat0 (196 floats/row, 16B-aligned rows) -------
__global__ void pool0_kernel(const float* __restrict__ feat) {
    int row  = blockIdx.x * 8 + (threadIdx.x >> 5);   // warp per (b,c) row
    int lane = threadIdx.x & 31;
    const float4* p = reinterpret_cast<const float4*>(feat + (size_t)row * HW0);
    float4 v = p[lane];                                // 49 float4 per row
    float s = v.x + v.y + v.z + v.w;
    if (lane < 17) {
        float4 w = p[32 + lane];
        s += w.x + w.y + w.z + w.w;
    }
    #pragma unroll
    for (int o = 16; o > 0; o >>= 1) s += __shfl_down_sync(0xffffffffu, s, o);
    if (lane == 0) g_pooled0[row] = s * (1.0f / 196.0f);
}

// ---------------- pooling: feat1 (49 floats/row) ---------------------------
__global__ void pool1_kernel(const float* __restrict__ feat) {
    int row  = blockIdx.x * 8 + (threadIdx.x >> 5);
    int lane = threadIdx.x & 31;
    const float* p = feat + (size_t)row * HW1;
    float s = p[lane];                 // lanes 0..31 all valid (49 > 32)
    if (lane < 17) s += p[32 + lane];
    #pragma unroll
    for (int o = 16; o > 0; o >>= 1) s += __shfl_down_sync(0xffffffffu, s, o);
    if (lane == 0) g_pooled1[row] = s * (1.0f / 49.0f);
}

// ---------------- heads: logits + weighted CE per sample -------------------
// grid: [BATCH/BPB blocks for head0] + [BATCH/BPB blocks for head1], 128 thr
__global__ void head_kernel(const float* __restrict__ W0, const float* __restrict__ b0,
                            const float* __restrict__ W1, const float* __restrict__ b1,
                            const int*   __restrict__ lut0, const int* __restrict__ lut1,
                            const float* __restrict__ cw0, const float* __restrict__ cw1,
                            const int*   __restrict__ target) {
    __shared__ float sp[BPB * C1];     // 32 KB max (head1); head0 uses first 16 KB
    __shared__ float slog[BPB * 128];  // padded logits

    const int  nb0   = BATCH / BPB;
    const bool head  = (blockIdx.x >= nb0);
    const int  bbase = (head ? (blockIdx.x - nb0) : blockIdx.x) * BPB;

    const int    C    = head ? C1 : C0;
    const int    K    = head ? K1 : K0;
    const float* pooled = head ? g_pooled1 : g_pooled0;
    const float* W    = head ? W1 : W0;
    const float* bias = head ? b1 : b0;
    const int*   lut  = head ? lut1 : lut0;
    const float* cw   = head ? cw1 : cw0;

    const int t = threadIdx.x;

    // stage BPB pooled rows (contiguous in g_pooled) into smem, float4
    {
        const float4* src = reinterpret_cast<const float4*>(pooled + (size_t)bbase * C);
        float4* dst = reinterpret_cast<float4*>(sp);
        const int n4 = (BPB * C) >> 2;
        for (int i = t; i < n4; i += 128) dst[i] = src[i];
    }
    __syncthreads();

    // each thread t < K computes BPB logits for cluster t
    float acc[BPB];
    if (t < K) {
        #pragma unroll
        for (int j = 0; j < BPB; j++) acc[j] = 0.0f;
        const float4* w4 = reinterpret_cast<const float4*>(W + (size_t)t * C);
        const int C4 = C >> 2;
        for (int c4 = 0; c4 < C4; c4++) {
            float4 wv = __ldg(w4 + c4);
            #pragma unroll
            for (int j = 0; j < BPB; j++) {
                float4 pv = *reinterpret_cast<const float4*>(&sp[j * C + (c4 << 2)]);
                acc[j] = fmaf(pv.x, wv.x,
                         fmaf(pv.y, wv.y,
                         fmaf(pv.z, wv.z,
                         fmaf(pv.w, wv.w, acc[j]))));
            }
        }
        float bv = bias[t];
        #pragma unroll
        for (int j = 0; j < BPB; j++) acc[j] += bv;
    }
    #pragma unroll
    for (int j = 0; j < BPB; j++)
        slog[j * 128 + t] = (t < K) ? acc[j] : -INFINITY;
    __syncthreads();

    // warp-per-batch log-sum-exp + weighted NLL
    const int warp = t >> 5, lane = t & 31;
    for (int j = warp; j < BPB; j += 4) {
        float v0 = slog[j * 128 + lane];
        float v1 = slog[j * 128 + lane + 32];
        float v2 = slog[j * 128 + lane + 64];
        float v3 = slog[j * 128 + lane + 96];
        float mx = fmaxf(fmaxf(v0, v1), fmaxf(v2, v3));
        #pragma unroll
        for (int o = 16; o > 0; o >>= 1)
            mx = fmaxf(mx, __shfl_xor_sync(0xffffffffu, mx, o));
        float se = expf(v0 - mx) + expf(v1 - mx) + expf(v2 - mx) + expf(v3 - mx);
        #pragma unroll
        for (int o = 16; o > 0; o >>= 1)
            se += __shfl_xor_sync(0xffffffffu, se, o);
        if (lane == 0) {
            float lse  = mx + logf(se);
            int   bidx = bbase + j;
            int   tc   = lut[target[bidx]];
            float nll  = lse - slog[j * 128 + tc];
            float w    = cw[tc];
            g_nll[(head ? BATCH : 0) + bidx] = w * nll;
            g_ws [(head ? BATCH : 0) + bidx] = w;
        }
    }
}

// ---------------- final deterministic reduction -----------------------------
__global__ void finalize_kernel(float* __restrict__ out) {
    __shared__ float red[256];
    const int t = threadIdx.x;
    float n0 = 0.f, w0 = 0.f, n1 = 0.f, w1 = 0.f;
    for (int i = t; i < BATCH; i += 256) {
        n0 += g_nll[i];         w0 += g_ws[i];
        n1 += g_nll[BATCH + i]; w1 += g_ws[BATCH + i];
    }
    auto block_reduce = [&](float v) -> float {
        red[t] = v; __syncthreads();
        for (int s = 128; s > 0; s >>= 1) {
            if (t < s) red[t] += red[t + s];
            __syncthreads();
        }
        float r = red[0]; __syncthreads();
        return r;
    };
    n0 = block_reduce(n0);
    w0 = block_reduce(w0);
    n1 = block_reduce(n1);
    w1 = block_reduce(w1);
    if (t == 0) out[0] = n0 / w0 + n1 / w1;
}

// ---------------- launch ----------------------------------------------------
extern "C" void kernel_launch(void* const* d_in, const int* in_sizes, int n_in,
                              void* d_out, int out_size) {
    const float* feat0  = (const float*)d_in[0];
    const float* feat1  = (const float*)d_in[1];
    const float* W0     = (const float*)d_in[2];
    const float* b0     = (const float*)d_in[3];
    const float* W1     = (const float*)d_in[4];
    const float* b1     = (const float*)d_in[5];
    const int*   lut0   = (const int*)  d_in[6];
    const int*   lut1   = (const int*)  d_in[7];
    const float* cw0    = (const float*)d_in[8];
    const float* cw1    = (const float*)d_in[9];
    const int*   target = (const int*)  d_in[10];

    // pool0: 1024*512 rows, 8 warps/block
    pool0_kernel<<<(BATCH * C0) / 8, 256>>>(feat0);
    // pool1: 1024*1024 rows
    pool1_kernel<<<(BATCH * C1) / 8, 256>>>(feat1);
    // heads: 128 blocks head0 + 128 blocks head1
    head_kernel<<<2 * (BATCH / BPB), 128>>>(W0, b0, W1, b1,
                                            lut0, lut1, cw0, cw1, target);
    finalize_kernel<<<1, 256>>>((float*)d_out);
}

// round 2
// speedup vs baseline: 1.4167x; 1.4167x over previous
#include <cuda_runtime.h>
#include <math.h>

#define BATCH 1024
#define C0 512
#define HW0 196   /* 14*14 */
#define C1 1024
#define HW1 49    /* 7*7  */
#define K0 100
#define K1 50
#define BPB 8     /* batch rows per head block */

#define POOL_THREADS 128
#define CHUNK_FLOATS (POOL_THREADS * 49)      /* 6272 floats = 25088 B  */
#define CHUNK_F4     (CHUNK_FLOATS / 4)       /* 1568 float4            */
#define NB_POOL0     ((BATCH * C0) / 32)      /* 32 rows/block -> 16384 */
#define NB_POOL1     ((BATCH * C1) / 128)     /* 128 rows/block -> 8192 */

// ---------------- scratch (device globals; no allocation) ----------------
__device__ float g_pooled0[BATCH * C0];
__device__ float g_pooled1[BATCH * C1];
__device__ float g_pnll[2 * (BATCH / BPB)];   // per-head-block partial w*nll
__device__ float g_pws [2 * (BATCH / BPB)];   // per-head-block partial w

// ---------------- fused pooling: flat stream -> smem -> stride-49 sums ----
__global__ __launch_bounds__(POOL_THREADS) void pool_kernel(
        const float* __restrict__ feat0, const float* __restrict__ feat1) {
    __shared__ float sm[CHUNK_FLOATS];
    const int  t   = threadIdx.x;
    const bool is1 = (blockIdx.x >= NB_POOL0);
    const int  blk = is1 ? (blockIdx.x - NB_POOL0) : blockIdx.x;

    const float4* src = is1
        ? reinterpret_cast<const float4*>(feat1) + (size_t)blk * CHUNK_F4
        : reinterpret_cast<const float4*>(feat0) + (size_t)blk * CHUNK_F4;

    float4* d = reinterpret_cast<float4*>(sm);
    #pragma unroll
    for (int i = t; i < CHUNK_F4; i += POOL_THREADS)
        d[i] = __ldcs(src + i);
    __syncthreads();

    // thread t sums 49 floats at stride-49 base (odd stride -> conflict-free)
    const float* p = sm + 49 * t;
    float s0 = 0.f, s1 = 0.f, s2 = 0.f, s3 = 0.f;
    #pragma unroll
    for (int j = 0; j < 48; j += 4) {
        s0 += p[j]; s1 += p[j + 1]; s2 += p[j + 2]; s3 += p[j + 3];
    }
    float s = (s0 + s1) + (s2 + s3) + p[48];

    if (is1) {
        // one thread == one channel row of 49
        g_pooled1[blk * 128 + t] = s * (1.0f / 49.0f);
    } else {
        // 4 threads == one channel row of 196
        s += __shfl_down_sync(0xffffffffu, s, 2);
        s += __shfl_down_sync(0xffffffffu, s, 1);
        if ((t & 3) == 0)
            g_pooled0[blk * 32 + (t >> 2)] = s * (1.0f / 196.0f);
    }
}

// ---------------- heads: logits + weighted CE, block-level partials --------
__global__ __launch_bounds__(128) void head_kernel(
        const float* __restrict__ W0, const float* __restrict__ b0,
        const float* __restrict__ W1, const float* __restrict__ b1,
        const int*   __restrict__ lut0, const int* __restrict__ lut1,
        const float* __restrict__ cw0, const float* __restrict__ cw1,
        const int*   __restrict__ target) {
    __shared__ float sp[BPB * C1];     // 32 KB max (head1)
    __shared__ float slog[BPB * 128];
    __shared__ float s_nll[BPB], s_ws[BPB];

    const int  nb0   = BATCH / BPB;
    const bool head  = (blockIdx.x >= nb0);
    const int  bbase = (head ? (blockIdx.x - nb0) : blockIdx.x) * BPB;

    const int    C      = head ? C1 : C0;
    const int    K      = head ? K1 : K0;
    const float* pooled = head ? g_pooled1 : g_pooled0;
    const float* W      = head ? W1 : W0;
    const float* bias   = head ? b1 : b0;
    const int*   lut    = head ? lut1 : lut0;
    const float* cw     = head ? cw1 : cw0;

    const int t = threadIdx.x;

    {   // stage BPB pooled rows into smem
        const float4* src = reinterpret_cast<const float4*>(pooled + (size_t)bbase * C);
        float4* dst = reinterpret_cast<float4*>(sp);
        const int n4 = (BPB * C) >> 2;
        for (int i = t; i < n4; i += 128) dst[i] = src[i];
    }
    __syncthreads();

    // thread t < K: BPB logits for cluster t
    float acc[BPB];
    if (t < K) {
        #pragma unroll
        for (int j = 0; j < BPB; j++) acc[j] = 0.0f;
        const float4* w4 = reinterpret_cast<const float4*>(W + (size_t)t * C);
        const int C4 = C >> 2;
        for (int c4 = 0; c4 < C4; c4++) {
            float4 wv = __ldg(w4 + c4);
            #pragma unroll
            for (int j = 0; j < BPB; j++) {
                float4 pv = *reinterpret_cast<const float4*>(&sp[j * C + (c4 << 2)]);
                acc[j] = fmaf(pv.x, wv.x,
                         fmaf(pv.y, wv.y,
                         fmaf(pv.z, wv.z,
                         fmaf(pv.w, wv.w, acc[j]))));
            }
        }
        float bv = bias[t];
        #pragma unroll
        for (int j = 0; j < BPB; j++) acc[j] += bv;
    }
    #pragma unroll
    for (int j = 0; j < BPB; j++)
        slog[j * 128 + t] = (t < K) ? acc[j] : -INFINITY;
    __syncthreads();

    // warp-per-batch log-sum-exp + weighted NLL
    const int warp = t >> 5, lane = t & 31;
    for (int j = warp; j < BPB; j += 4) {
        float v0 = slog[j * 128 + lane];
        float v1 = slog[j * 128 + lane + 32];
        float v2 = slog[j * 128 + lane + 64];
        float v3 = slog[j * 128 + lane + 96];
        float mx = fmaxf(fmaxf(v0, v1), fmaxf(v2, v3));
        #pragma unroll
        for (int o = 16; o > 0; o >>= 1)
            mx = fmaxf(mx, __shfl_xor_sync(0xffffffffu, mx, o));
        float se = expf(v0 - mx) + expf(v1 - mx) + expf(v2 - mx) + expf(v3 - mx);
        #pragma unroll
        for (int o = 16; o > 0; o >>= 1)
            se += __shfl_xor_sync(0xffffffffu, se, o);
        if (lane == 0) {
            float lse  = mx + logf(se);
            int   bidx = bbase + j;
            int   tc   = lut[target[bidx]];
            float nll  = lse - slog[j * 128 + tc];
            float w    = cw[tc];
            s_nll[j] = w * nll;
            s_ws [j] = w;
        }
    }
    __syncthreads();
    if (t == 0) {
        float pn = 0.f, pw = 0.f;
        #pragma unroll
        for (int j = 0; j < BPB; j++) { pn += s_nll[j]; pw += s_ws[j]; }
        g_pnll[blockIdx.x] = pn;
        g_pws [blockIdx.x] = pw;
    }
}

// ---------------- final deterministic reduction (512 floats) ---------------
__global__ void finalize_kernel(float* __restrict__ out) {
    __shared__ float red[4][4];
    const int t = threadIdx.x;          // 128 threads
    const int warp = t >> 5, lane = t & 31;
    float n0 = g_pnll[t],       w0 = g_pws[t];
    float n1 = g_pnll[128 + t], w1 = g_pws[128 + t];
    #pragma unroll
    for (int o = 16; o > 0; o >>= 1) {
        n0 += __shfl_down_sync(0xffffffffu, n0, o);
        w0 += __shfl_down_sync(0xffffffffu, w0, o);
        n1 += __shfl_down_sync(0xffffffffu, n1, o);
        w1 += __shfl_down_sync(0xffffffffu, w1, o);
    }
    if (lane == 0) {
        red[warp][0] = n0; red[warp][1] = w0;
        red[warp][2] = n1; red[warp][3] = w1;
    }
    __syncthreads();
    if (t == 0) {
        float a = 0.f, b = 0.f, c = 0.f, d = 0.f;
        #pragma unroll
        for (int w = 0; w < 4; w++) {
            a += red[w][0]; b += red[w][1];
            c += red[w][2]; d += red[w][3];
        }
        out[0] = a / b + c / d;
    }
}

// ---------------- launch ----------------------------------------------------
extern "C" void kernel_launch(void* const* d_in, const int* in_sizes, int n_in,
                              void* d_out, int out_size) {
    const float* feat0  = (const float*)d_in[0];
    const float* feat1  = (const float*)d_in[1];
    const float* W0     = (const float*)d_in[2];
    const float* b0     = (const float*)d_in[3];
    const float* W1     = (const float*)d_in[4];
    const float* b1     = (const float*)d_in[5];
    const int*   lut0   = (const int*)  d_in[6];
    const int*   lut1   = (const int*)  d_in[7];
    const float* cw0    = (const float*)d_in[8];
    const float* cw1    = (const float*)d_in[9];
    const int*   target = (const int*)  d_in[10];

    pool_kernel<<<NB_POOL0 + NB_POOL1, POOL_THREADS>>>(feat0, feat1);
    head_kernel<<<2 * (BATCH / BPB), 128>>>(W0, b0, W1, b1,
                                            lut0, lut1, cw0, cw1, target);
    finalize_kernel<<<1, 128>>>((float*)d_out);
}

// round 3
// speedup vs baseline: 1.5046x; 1.0620x over previous
#include <cuda_runtime.h>
#include <math.h>
#include <stdint.h>

#define BATCH 1024
#define C0 512
#define HW0 196   /* 14*14 */
#define C1 1024
#define HW1 49    /* 7*7  */
#define K0 100
#define K1 50
#define BPB 8     /* batch rows per head block */

#define POOL_THREADS 128
#define CHUNK_FLOATS (POOL_THREADS * 49)      /* 6272 floats = 25088 B  */
#define CHUNK_BYTES  (CHUNK_FLOATS * 4)
#define NB_POOL0     ((BATCH * C0) / 32)      /* 16384 chunks for feat0 */
#define NB_POOL1     ((BATCH * C1) / 128)     /* 8192 chunks for feat1  */
#define NCHUNKS      (NB_POOL0 + NB_POOL1)    /* 24576 */
#define POOL_GRID    592                       /* 4 blocks/SM x 148 SM  */

#define NHB (2 * (BATCH / BPB))               /* 256 head blocks */

// ---------------- scratch (device globals; no allocation) ----------------
__device__ float g_pooled0[BATCH * C0];
__device__ float g_pooled1[BATCH * C1];
__device__ float g_pnll[NHB];
__device__ float g_pws [NHB];
__device__ int   g_count;

// ---------------- PTX helpers ---------------------------------------------
__device__ __forceinline__ uint32_t smem_u32(const void* p) {
    uint32_t a;
    asm("{ .reg .u64 t; cvta.to.shared.u64 t, %1; cvt.u32.u64 %0, t; }"
        : "=r"(a) : "l"(p));
    return a;
}
#define MBAR_INIT(a, c) \
    asm volatile("mbarrier.init.shared.b64 [%0], %1;" :: "r"(a), "r"(c) : "memory")
#define MBAR_EXPECT_TX(a, b) \
    asm volatile("mbarrier.arrive.expect_tx.shared.b64 _, [%0], %1;" :: "r"(a), "r"(b) : "memory")
#define BULK_G2S(dst, src, bytes, mbar) \
    asm volatile("cp.async.bulk.shared::cluster.global.mbarrier::complete_tx::bytes " \
                 "[%0], [%1], %2, [%3];" \
                 :: "r"(dst), "l"(src), "r"(bytes), "r"(mbar) : "memory")
__device__ __forceinline__ void mbar_wait(uint32_t mbar, uint32_t parity) {
    asm volatile(
        "{\n\t.reg .pred P;\n\t"
        "WL_%=:\n\t"
        "mbarrier.try_wait.parity.acquire.cta.shared::cta.b64 P, [%0], %1, 0x989680;\n\t"
        "@P bra.uni WD_%=;\n\t"
        "bra.uni WL_%=;\n\t"
        "WD_%=:\n\t}"
        :: "r"(mbar), "r"(parity) : "memory");
}
#define FMA2(acc, a, b) \
    asm("fma.rn.f32x2 %0, %1, %2, %0;" : "+l"(acc) : "l"(a), "l"(b))

// ---------------- pooling: bulk-async double-buffered persistent -----------
__global__ __launch_bounds__(POOL_THREADS) void pool_kernel(
        const float* __restrict__ feat0, const float* __restrict__ feat1) {
    extern __shared__ __align__(128) char smem[];
    float* buf[2] = { (float*)smem, (float*)(smem + CHUNK_BYTES) };
    uint32_t mbar[2] = { smem_u32(smem + 2 * CHUNK_BYTES),
                         smem_u32(smem + 2 * CHUNK_BYTES + 8) };
    const int t   = threadIdx.x;
    const int bid = blockIdx.x;

    if (bid == 0 && t == 0) g_count = 0;   // reset fused-finalize counter

    if (t == 0) { MBAR_INIT(mbar[0], 1); MBAR_INIT(mbar[1], 1); }
    __syncthreads();

    // issue a chunk copy into buffer bb
    auto issue = [&](int chunk, int bb) {
        const char* src = (chunk < NB_POOL0)
            ? (const char*)feat0 + (size_t)chunk * CHUNK_BYTES
            : (const char*)feat1 + (size_t)(chunk - NB_POOL0) * CHUNK_BYTES;
        MBAR_EXPECT_TX(mbar[bb], CHUNK_BYTES);
        BULK_G2S(smem_u32(buf[bb]), src, CHUNK_BYTES, mbar[bb]);
    };

    // prologue: fill both buffers
    if (t == 0) {
        if (bid < NCHUNKS)             issue(bid, 0);
        if (bid + POOL_GRID < NCHUNKS) issue(bid + POOL_GRID, 1);
    }

    int parity[2] = { 0, 0 };
    int it = 0;
    for (int chunk = bid; chunk < NCHUNKS; chunk += POOL_GRID, it++) {
        const int bb = it & 1;
        mbar_wait(mbar[bb], parity[bb]);
        parity[bb] ^= 1;

        // thread t sums 49 floats at stride-49 (odd -> bank-conflict-free)
        const float* p = buf[bb] + 49 * t;
        float s0 = 0.f, s1 = 0.f, s2 = 0.f, s3 = 0.f;
        #pragma unroll
        for (int j = 0; j < 48; j += 4) {
            s0 += p[j]; s1 += p[j + 1]; s2 += p[j + 2]; s3 += p[j + 3];
        }
        float s = (s0 + s1) + (s2 + s3) + p[48];

        if (chunk < NB_POOL0) {
            s += __shfl_down_sync(0xffffffffu, s, 2);
            s += __shfl_down_sync(0xffffffffu, s, 1);
            if ((t & 3) == 0)
                g_pooled0[chunk * 32 + (t >> 2)] = s * (1.0f / 196.0f);
        } else {
            g_pooled1[(chunk - NB_POOL0) * 128 + t] = s * (1.0f / 49.0f);
        }

        __syncthreads();   // everyone done reading buf[bb]
        if (t == 0 && chunk + 2 * POOL_GRID < NCHUNKS)
            issue(chunk + 2 * POOL_GRID, bb);
    }
}

// ---------------- heads: f32x2 logits + weighted CE + fused finalize -------
__global__ __launch_bounds__(128) void head_kernel(
        const float* __restrict__ W0, const float* __restrict__ b0,
        const float* __restrict__ W1, const float* __restrict__ b1,
        const int*   __restrict__ lut0, const int* __restrict__ lut1,
        const float* __restrict__ cw0, const float* __restrict__ cw1,
        const int*   __restrict__ target) {
    __shared__ float sp[BPB * C1];     // 32 KB max (head1)
    __shared__ float slog[BPB * 128];
    __shared__ float s_nll[BPB], s_ws[BPB];
    __shared__ int   s_last;

    const int  nb0   = BATCH / BPB;
    const bool head  = (blockIdx.x >= nb0);
    const int  bbase = (head ? (blockIdx.x - nb0) : blockIdx.x) * BPB;

    const int    C      = head ? C1 : C0;
    const int    K      = head ? K1 : K0;
    const float* pooled = head ? g_pooled1 : g_pooled0;
    const float* W      = head ? W1 : W0;
    const float* bias   = head ? b1 : b0;
    const int*   lut    = head ? lut1 : lut0;
    const float* cw     = head ? cw1 : cw0;

    const int t = threadIdx.x;

    {   // stage BPB pooled rows into smem
        const float4* src = reinterpret_cast<const float4*>(pooled + (size_t)bbase * C);
        float4* dst = reinterpret_cast<float4*>(sp);
        const int n4 = (BPB * C) >> 2;
        for (int i = t; i < n4; i += 128) dst[i] = src[i];
    }
    __syncthreads();

    // thread t < K: BPB logits for cluster t using packed f32x2 FMA
    float logit[BPB];
    if (t < K) {
        uint64_t accA[BPB], accB[BPB];
        #pragma unroll
        for (int j = 0; j < BPB; j++) { accA[j] = 0ull; accB[j] = 0ull; }
        const ulonglong2* w2 = reinterpret_cast<const ulonglong2*>(W + (size_t)t * C);
        const int C4 = C >> 2;
        for (int c4 = 0; c4 < C4; c4++) {
            ulonglong2 wv = __ldg(w2 + c4);
            #pragma unroll
            for (int j = 0; j < BPB; j++) {
                ulonglong2 pv = *reinterpret_cast<const ulonglong2*>(&sp[j * C + (c4 << 2)]);
                FMA2(accA[j], pv.x, wv.x);
                FMA2(accB[j], pv.y, wv.y);
            }
        }
        float bv = bias[t];
        #pragma unroll
        for (int j = 0; j < BPB; j++) {
            float ax = __uint_as_float((uint32_t)accA[j]);
            float ay = __uint_as_float((uint32_t)(accA[j] >> 32));
            float bx = __uint_as_float((uint32_t)accB[j]);
            float by = __uint_as_float((uint32_t)(accB[j] >> 32));
            logit[j] = (ax + ay) + (bx + by) + bv;
        }
    }
    #pragma unroll
    for (int j = 0; j < BPB; j++)
        slog[j * 128 + t] = (t < K) ? logit[j] : -INFINITY;
    __syncthreads();

    // warp-per-batch log-sum-exp + weighted NLL
    const int warp = t >> 5, lane = t & 31;
    for (int j = warp; j < BPB; j += 4) {
        float v0 = slog[j * 128 + lane];
        float v1 = slog[j * 128 + lane + 32];
        float v2 = slog[j * 128 + lane + 64];
        float v3 = slog[j * 128 + lane + 96];
        float mx = fmaxf(fmaxf(v0, v1), fmaxf(v2, v3));
        #pragma unroll
        for (int o = 16; o > 0; o >>= 1)
            mx = fmaxf(mx, __shfl_xor_sync(0xffffffffu, mx, o));
        float se = expf(v0 - mx) + expf(v1 - mx) + expf(v2 - mx) + expf(v3 - mx);
        #pragma unroll
        for (int o = 16; o > 0; o >>= 1)
            se += __shfl_xor_sync(0xffffffffu, se, o);
        if (lane == 0) {
            float lse  = mx + logf(se);
            int   bidx = bbase + j;
            int   tc   = lut[target[bidx]];
            float nll  = lse - slog[j * 128 + tc];
            float w    = cw[tc];
            s_nll[j] = w * nll;
            s_ws [j] = w;
        }
    }
    __syncthreads();
    if (t == 0) {
        float pn = 0.f, pw = 0.f;
        #pragma unroll
        for (int j = 0; j < BPB; j++) { pn += s_nll[j]; pw += s_ws[j]; }
        g_pnll[blockIdx.x] = pn;
        g_pws [blockIdx.x] = pw;
        __threadfence();
        s_last = (atomicAdd(&g_count, 1) == NHB - 1);
    }
    __syncthreads();

    // last block performs the final deterministic reduction
    if (s_last) {
        float* out = (float*)0;  // patched below via constant? no: passed via slog trick
        // reuse slog as reduction scratch
        float n0 = g_pnll[t],        w0 = g_pws[t];
        float n1 = g_pnll[128 + t],  w1 = g_pws[128 + t];
        #pragma unroll
        for (int o = 16; o > 0; o >>= 1) {
            n0 += __shfl_down_sync(0xffffffffu, n0, o);
            w0 += __shfl_down_sync(0xffffffffu, w0, o);
            n1 += __shfl_down_sync(0xffffffffu, n1, o);
            w1 += __shfl_down_sync(0xffffffffu, w1, o);
        }
        if (lane == 0) {
            slog[warp * 4 + 0] = n0; slog[warp * 4 + 1] = w0;
            slog[warp * 4 + 2] = n1; slog[warp * 4 + 3] = w1;
        }
        __syncthreads();
        if (t == 0) {
            float a = 0.f, b = 0.f, c = 0.f, d = 0.f;
            #pragma unroll
            for (int w = 0; w < 4; w++) {
                a += slog[w * 4 + 0]; b += slog[w * 4 + 1];
                c += slog[w * 4 + 2]; d += slog[w * 4 + 3];
            }
            // out pointer is stored in g_outp by host-launched param; see below
            extern __device__ float* g_outp;
            g_outp[0] = a / b + c / d;
        }
    }
    (void)0;
}

__device__ float* g_outp;

__global__ void set_outp_kernel(float* out) { g_outp = out; }

// ---------------- launch ----------------------------------------------------
extern "C" void kernel_launch(void* const* d_in, const int* in_sizes, int n_in,
                              void* d_out, int out_size) {
    const float* feat0  = (const float*)d_in[0];
    const float* feat1  = (const float*)d_in[1];
    const float* W0     = (const float*)d_in[2];
    const float* b0     = (const float*)d_in[3];
    const float* W1     = (const float*)d_in[4];
    const float* b1     = (const float*)d_in[5];
    const int*   lut0   = (const int*)  d_in[6];
    const int*   lut1   = (const int*)  d_in[7];
    const float* cw0    = (const float*)d_in[8];
    const float* cw1    = (const float*)d_in[9];
    const int*   target = (const int*)  d_in[10];

    static bool attr_set = false;
    if (!attr_set) {
        cudaFuncSetAttribute(pool_kernel,
                             cudaFuncAttributeMaxDynamicSharedMemorySize,
                             2 * CHUNK_BYTES + 128);
        attr_set = true;
    }

    set_outp_kernel<<<1, 1>>>((float*)d_out);
    pool_kernel<<<POOL_GRID, POOL_THREADS, 2 * CHUNK_BYTES + 128>>>(feat0, feat1);
    head_kernel<<<NHB, 128>>>(W0, b0, W1, b1, lut0, lut1, cw0, cw1, target);
}